// round 1
// baseline (speedup 1.0000x reference)
#include <cuda_runtime.h>
#include <math.h>

// h = W2 @ gelu(W1 @ bp + b1) + b2, broadcast to all 64 batch rows.
// (fmean of time-standardized features is exactly 0 in exact arithmetic;
//  reference's fmean is ~1e-8 fp32 noise -> negligible vs rel_err 1e-3.)

#define DIM   256
#define HID   512
#define BATCH 64

__device__ float g_hidden[HID];

// ---------------------------------------------------------------------------
// Phase 1: g[j] = gelu( dot(W1[j, 0:256], bp) + b1[j] ), j in [0, 512)
// One warp per output row; coalesced float4 loads; shuffle reduction.
// ---------------------------------------------------------------------------
__global__ void __launch_bounds__(256)
phase1_kernel(const float* __restrict__ W1,
              const float* __restrict__ b1,
              const float* __restrict__ bp)
{
    int gwarp = (blockIdx.x * blockDim.x + threadIdx.x) >> 5;
    int lane  = threadIdx.x & 31;
    if (gwarp >= HID) return;

    const float4* row = reinterpret_cast<const float4*>(W1 + gwarp * DIM);
    const float4* vec = reinterpret_cast<const float4*>(bp);

    float acc = 0.0f;
#pragma unroll
    for (int i = 0; i < DIM / 4 / 32; ++i) {   // 2 iterations
        float4 w = row[lane + 32 * i];
        float4 x = vec[lane + 32 * i];
        acc += w.x * x.x + w.y * x.y + w.z * x.z + w.w * x.w;
    }
#pragma unroll
    for (int off = 16; off > 0; off >>= 1)
        acc += __shfl_xor_sync(0xffffffffu, acc, off);

    if (lane == 0) {
        float x = acc + b1[gwarp];
        // exact GELU (jax.nn.gelu approximate=False): 0.5*x*(1+erf(x/sqrt(2)))
        float g = 0.5f * x * (1.0f + erff(x * 0.7071067811865475f));
        g_hidden[gwarp] = g;
    }
}

// ---------------------------------------------------------------------------
// Phase 2: o[d] = dot(W2[d, 0:512], g) + b2[d], d in [0, 256)
// One warp per output; broadcast o[d] to out[b*256 + d] for all 64 b.
// ---------------------------------------------------------------------------
__global__ void __launch_bounds__(256)
phase2_kernel(const float* __restrict__ W2,
              const float* __restrict__ b2,
              float* __restrict__ out)
{
    int gwarp = (blockIdx.x * blockDim.x + threadIdx.x) >> 5;
    int lane  = threadIdx.x & 31;
    if (gwarp >= DIM) return;

    const float4* row = reinterpret_cast<const float4*>(W2 + gwarp * HID);
    const float4* vec = reinterpret_cast<const float4*>(g_hidden);

    float acc = 0.0f;
#pragma unroll
    for (int i = 0; i < HID / 4 / 32; ++i) {   // 4 iterations
        float4 w = row[lane + 32 * i];
        float4 x = vec[lane + 32 * i];
        acc += w.x * x.x + w.y * x.y + w.z * x.z + w.w * x.w;
    }
#pragma unroll
    for (int off = 16; off > 0; off >>= 1)
        acc += __shfl_xor_sync(0xffffffffu, acc, off);

    float o = acc + b2[gwarp];
    o = __shfl_sync(0xffffffffu, o, 0);

    // 64 batch rows: lane writes rows {lane, lane+32}
    out[lane * DIM + gwarp]        = o;
    out[(lane + 32) * DIM + gwarp] = o;
}

// ---------------------------------------------------------------------------
extern "C" void kernel_launch(void* const* d_in, const int* in_sizes, int n_in,
                              void* d_out, int out_size)
{
    // Expected metadata order:
    // 0..4: close, high, low, open_price, volume  (64*65536 each, unused)
    // 5: Wp(1280)  6: bp(256)  7: W1(131072)  8: b1(512)  9: W2(131072)  10: b2(256)
    int pi = 5;
    for (int i = 0; i < n_in; ++i) {
        if (in_sizes[i] == 1280) { pi = i; break; }  // locate Wp robustly
    }
    const float* bp = (const float*)d_in[pi + 1];
    const float* W1 = (const float*)d_in[pi + 2];
    const float* b1 = (const float*)d_in[pi + 3];
    const float* W2 = (const float*)d_in[pi + 4];
    const float* b2 = (const float*)d_in[pi + 5];
    float* out = (float*)d_out;

    // phase1: 512 warps -> 64 blocks x 256 threads
    phase1_kernel<<<64, 256>>>(W1, b1, bp);
    // phase2: 256 warps -> 32 blocks x 256 threads
    phase2_kernel<<<32, 256>>>(W2, b2, out);
}

// round 2
// speedup vs baseline: 1.0949x; 1.0949x over previous
#include <cuda_runtime.h>
#include <math.h>

// h = W2 @ gelu(W1 @ bp + b1) + b2, broadcast to all 64 batch rows.
// (fmean of time-standardized features is exactly 0 in exact arithmetic;
//  the reference's fmean is ~1e-8 fp32 summation noise -> ~1e-6 rel effect.)
//
// Single fused kernel:
//   64 blocks x 256 threads = 512 warps.
//   Phase 1: warp gw computes g[gw] = gelu(dot(W1[gw,:], bp) + b1[gw]).
//   Grid barrier (monotonic ticket counter -> replay-safe, no reset).
//   Phase 2: blocks 0..31 (warps 0..255): out row ow = dot(W2[ow,:], g) + b2[ow],
//            broadcast to all 64 batch rows. W2 row is PRELOADED into registers
//            before phase 1 so its DRAM latency overlaps phase-1 work.

#define DIM    256
#define HID    512
#define NBLK   64
#define NTHR   256

__device__ float        g_hidden[HID];
__device__ unsigned int g_ticket;   // zero-init; monotonic across graph replays

__global__ void __launch_bounds__(NTHR)
fused_mlp_kernel(const float* __restrict__ bp,
                 const float* __restrict__ W1,
                 const float* __restrict__ b1,
                 const float* __restrict__ W2,
                 const float* __restrict__ b2,
                 float* __restrict__ out)
{
    const int warp = threadIdx.x >> 5;
    const int lane = threadIdx.x & 31;
    const int gw   = blockIdx.x * 8 + warp;          // 0..511
    const bool doP2 = (blockIdx.x < NBLK / 2);       // blocks 0..31 do phase 2
    const int  ow   = gw;                            // phase-2 output index (0..255)

    // ---- Prefetch phase-2 operands (independent of g) BEFORE phase 1 ----
    float4 w2r[4];
    float  b2v = 0.0f;
    if (doP2) {
        const float4* r2 = reinterpret_cast<const float4*>(W2 + ow * HID);
#pragma unroll
        for (int i = 0; i < 4; ++i) w2r[i] = __ldg(&r2[lane + 32 * i]);
        b2v = __ldg(&b2[ow]);
    }

    // ---- Phase 1: g[gw] = gelu(W1[gw,:] . bp + b1[gw]) ----
    {
        const float4* row = reinterpret_cast<const float4*>(W1 + gw * DIM);
        const float4* vec = reinterpret_cast<const float4*>(bp);
        float acc = 0.0f;
#pragma unroll
        for (int i = 0; i < 2; ++i) {
            float4 w = __ldg(&row[lane + 32 * i]);
            float4 x = __ldg(&vec[lane + 32 * i]);
            acc += w.x * x.x + w.y * x.y + w.z * x.z + w.w * x.w;
        }
#pragma unroll
        for (int off = 16; off > 0; off >>= 1)
            acc += __shfl_xor_sync(0xffffffffu, acc, off);
        if (lane == 0) {
            float x = acc + __ldg(&b1[gw]);
            // exact GELU (approximate=False): 0.5*x*(1+erf(x/sqrt(2)))
            g_hidden[gw] = 0.5f * x * (1.0f + erff(x * 0.7071067811865475f));
        }
    }

    // ---- Grid barrier: monotonic ticket counter (wrap-safe, replay-safe) ----
    __syncthreads();                 // block's g_hidden stores issued
    __shared__ unsigned int s_go;    // dummy to force all threads through
    if (threadIdx.x == 0) {
        __threadfence();             // publish g_hidden before arrival
        unsigned int t = atomicAdd(&g_ticket, 1u) + 1u;
        // round ticket up to the next multiple of NBLK = this launch's target
        unsigned int target = ((t + NBLK - 1u) / NBLK) * NBLK;
        if (doP2) {
            while ((int)(atomicAdd(&g_ticket, 0u) - target) < 0) {
                __nanosleep(32);
            }
        }
        s_go = target;               // any value; just a dependency
    }
    __syncthreads();

    if (!doP2) return;               // non-phase-2 blocks exit after arriving
    __threadfence();                 // acquire: order g_hidden reads after spin

    // ---- Phase 2: out row ow = W2[ow,:] . g + b2[ow], broadcast 64 rows ----
    {
        const float4* vec = reinterpret_cast<const float4*>(g_hidden);
        float acc = 0.0f;
#pragma unroll
        for (int i = 0; i < 4; ++i) {
            float4 x = vec[lane + 32 * i];
            acc += w2r[i].x * x.x + w2r[i].y * x.y
                 + w2r[i].z * x.z + w2r[i].w * x.w;
        }
#pragma unroll
        for (int off = 16; off > 0; off >>= 1)
            acc += __shfl_xor_sync(0xffffffffu, acc, off);

        float o = __shfl_sync(0xffffffffu, acc, 0) + b2v;

        // 64 identical batch rows: lane writes rows {lane, lane+32}
        out[lane * DIM + ow]        = o;
        out[(lane + 32) * DIM + ow] = o;
    }
}

// ---------------------------------------------------------------------------
extern "C" void kernel_launch(void* const* d_in, const int* in_sizes, int n_in,
                              void* d_out, int out_size)
{
    // 0..4: market arrays (unused). Locate Wp (1280 elems); params follow.
    int pi = 5;
    for (int i = 0; i < n_in; ++i)
        if (in_sizes[i] == 1280) { pi = i; break; }

    const float* bp = (const float*)d_in[pi + 1];
    const float* W1 = (const float*)d_in[pi + 2];
    const float* b1 = (const float*)d_in[pi + 3];
    const float* W2 = (const float*)d_in[pi + 4];
    const float* b2 = (const float*)d_in[pi + 5];
    float* out = (float*)d_out;

    fused_mlp_kernel<<<NBLK, NTHR>>>(bp, W1, b1, W2, b2, out);
}

// round 3
// speedup vs baseline: 1.3317x; 1.2163x over previous
#include <cuda_runtime.h>
#include <math.h>

// h = W2 @ gelu(W1 @ bp + b1) + b2, broadcast to all 64 batch rows.
// (fmean of time-standardized features is exactly 0 in exact arithmetic.)
//
// Single kernel, 64 blocks x 256 threads (512 warps):
//   phase 1: warp gw -> g[gw] = gelu(dot(W1[gw,:], bp) + b1[gw])
//   grid barrier: monotonic ticket, release-REDG arrivals, acquire-load spin
//   phase 2 (blocks 0..31): warp ow -> dot(W2[ow,:], g) + b2[ow];
//     W2 row prefetched into regs BEFORE the barrier (overlaps phase 1);
//     results exchanged via smem, stores fully sector-coalesced.

#define DIM    256
#define HID    512
#define NBLK   64
#define NTHR   256

__device__ float        g_hidden[HID];
__device__ unsigned int g_ticket;   // zero-init; monotonic across graph replays

__global__ void __launch_bounds__(NTHR)
fused_mlp_kernel(const float* __restrict__ bp,
                 const float* __restrict__ W1,
                 const float* __restrict__ b1,
                 const float* __restrict__ W2,
                 const float* __restrict__ b2,
                 float* __restrict__ out)
{
    const int warp = threadIdx.x >> 5;
    const int lane = threadIdx.x & 31;
    const int gw   = blockIdx.x * 8 + warp;          // 0..511 (phase-1 row)
    const bool doP2 = (blockIdx.x < NBLK / 2);       // blocks 0..31 run phase 2
    const int  ow   = gw;                            // phase-2 output (0..255)

    __shared__ float s_res[8];

    // ---- Issue phase-1 loads FIRST (they gate the barrier) ----
    const float4* row1 = reinterpret_cast<const float4*>(W1 + gw * DIM);
    const float4* vecb = reinterpret_cast<const float4*>(bp);
    float4 w1a = __ldg(&row1[lane]);
    float4 w1b = __ldg(&row1[lane + 32]);
    float4 xpa = __ldg(&vecb[lane]);
    float4 xpb = __ldg(&vecb[lane + 32]);
    float  b1v = __ldg(&b1[gw]);

    // ---- Then prefetch phase-2 operands (consumed only after barrier) ----
    float4 w2r[4];
    float  b2v = 0.0f;
    if (doP2) {
        const float4* row2 = reinterpret_cast<const float4*>(W2 + ow * HID);
#pragma unroll
        for (int i = 0; i < 4; ++i) w2r[i] = __ldg(&row2[lane + 32 * i]);
        b2v = __ldg(&b2[ow]);
    }

    // ---- Phase 1 reduce + GELU ----
    {
        float acc = w1a.x * xpa.x + w1a.y * xpa.y + w1a.z * xpa.z + w1a.w * xpa.w
                  + w1b.x * xpb.x + w1b.y * xpb.y + w1b.z * xpb.z + w1b.w * xpb.w;
#pragma unroll
        for (int off = 16; off > 0; off >>= 1)
            acc += __shfl_xor_sync(0xffffffffu, acc, off);
        if (lane == 0) {
            float x = acc + b1v;
            // exact GELU (approximate=False): 0.5*x*(1+erf(x/sqrt(2)))
            g_hidden[gw] = 0.5f * x * (1.0f + erff(x * 0.7071067811865475f));
        }
    }

    // ---- Grid barrier (monotonic ticket; release arrivals, acquire spin) ----
    __syncthreads();                      // all block g-stores program-ordered
    unsigned int* tick = &g_ticket;
    if (!doP2) {
        if (threadIdx.x == 0) {
            // fire-and-forget release arrival (no return-trip wait)
            asm volatile("red.release.gpu.global.add.u32 [%0], 1;"
                         :: "l"(tick) : "memory");
        }
        return;
    }

    if (threadIdx.x == 0) {
        unsigned int t;
        asm volatile("atom.acq_rel.gpu.global.add.u32 %0, [%1], 1;"
                     : "=r"(t) : "l"(tick) : "memory");
        t += 1u;
        unsigned int target = ((t + NBLK - 1u) / NBLK) * NBLK;  // this replay's goal
        unsigned int v;
        do {
            asm volatile("ld.acquire.gpu.global.u32 %0, [%1];"
                         : "=r"(v) : "l"(tick) : "memory");
        } while ((int)(v - target) < 0);
    }
    __syncthreads();                      // composes acquire block-wide

    // ---- Phase 2: dot(W2[ow,:], g) + b2 ----
    {
        const float4* vg = reinterpret_cast<const float4*>(g_hidden);
        float acc = 0.0f;
#pragma unroll
        for (int i = 0; i < 4; ++i) {
            float4 x = vg[lane + 32 * i];
            acc += w2r[i].x * x.x + w2r[i].y * x.y
                 + w2r[i].z * x.z + w2r[i].w * x.w;
        }
#pragma unroll
        for (int off = 16; off > 0; off >>= 1)
            acc += __shfl_xor_sync(0xffffffffu, acc, off);
        if (lane == 0) s_res[warp] = acc + b2v;
    }
    __syncthreads();

    // ---- Coalesced broadcast: block owns cols [blk*8, blk*8+8) of all 64 rows.
    // thread t: row r = t>>2, pair p = t&3 -> float2 at out[r*256 + blk*8 + 2p].
    {
        int r = threadIdx.x >> 2;
        int p = threadIdx.x & 3;
        float2 v = make_float2(s_res[2 * p], s_res[2 * p + 1]);
        float2* dst = reinterpret_cast<float2*>(out + r * DIM + blockIdx.x * 8 + 2 * p);
        *dst = v;
    }
}

// ---------------------------------------------------------------------------
extern "C" void kernel_launch(void* const* d_in, const int* in_sizes, int n_in,
                              void* d_out, int out_size)
{
    // 0..4: market arrays (unused). Locate Wp (1280 elems); params follow.
    int pi = 5;
    for (int i = 0; i < n_in; ++i)
        if (in_sizes[i] == 1280) { pi = i; break; }

    const float* bp = (const float*)d_in[pi + 1];
    const float* W1 = (const float*)d_in[pi + 2];
    const float* b1 = (const float*)d_in[pi + 3];
    const float* W2 = (const float*)d_in[pi + 4];
    const float* b2 = (const float*)d_in[pi + 5];
    float* out = (float*)d_out;

    fused_mlp_kernel<<<NBLK, NTHR>>>(bp, W1, b1, W2, b2, out);
}